// round 14
// baseline (speedup 1.0000x reference)
#include <cuda_runtime.h>
#include <math.h>
#include <stdint.h>

#define BB 64
#define SS 100
#define EE 512
#define HH 1024
#define VT 32000
#define NSPLIT 16
#define SCH 4
#define GRID 256

// ---------------- scratch ----------------
__device__ float g_mpart[SCH * BB * HH];
__device__ float g_mean[BB * HH];
__device__ float g_h0[BB * HH];
__device__ float g_en[BB * SS];
__device__ float g_cpart[SCH * BB * HH];
__device__ float g_x[BB * (EE + HH)];
__device__ float4 g_part[BB * (HH / 4) * NSPLIT];   // [(m*(N/4)+n4)*16 + p]
__device__ unsigned g_bar_cnt;

// ---------------- helpers ----------------
__device__ __forceinline__ uint32_t smem_u32(const void* p) {
    uint32_t a;
    asm("{ .reg .u64 t; cvta.to.shared.u64 t, %1; cvt.u32.u64 %0, t; }" : "=r"(a) : "l"(p));
    return a;
}
__device__ __forceinline__ uint32_t f2tf32(float x) {
    uint32_t u;
    asm("cvt.rna.tf32.f32 %0, %1;" : "=r"(u) : "f"(x));
    return u;
}
__device__ __forceinline__ void cp_async16(uint32_t saddr, const void* g) {
    asm volatile("cp.async.ca.shared.global [%0], [%1], 16;" :: "r"(saddr), "l"(g) : "memory");
}
__device__ __forceinline__ void cp_commit() {
    asm volatile("cp.async.commit_group;" ::: "memory");
}
__device__ __forceinline__ void cp_wait1() {
    asm volatile("cp.async.wait_group 1;" ::: "memory");
}
__device__ __forceinline__ void mma_tf32(float d[4], const uint32_t a[4], const uint32_t b[2]) {
    asm volatile(
        "mma.sync.aligned.m16n8k8.row.col.f32.tf32.tf32.f32 "
        "{%0,%1,%2,%3}, {%4,%5,%6,%7}, {%8,%9}, {%0,%1,%2,%3};"
        : "+f"(d[0]), "+f"(d[1]), "+f"(d[2]), "+f"(d[3])
        : "r"(a[0]), "r"(a[1]), "r"(a[2]), "r"(a[3]), "r"(b[0]), "r"(b[1]));
}
__device__ __forceinline__ float4 f4add(float4 a, float4 b) {
    return make_float4(a.x + b.x, a.y + b.y, a.z + b.z, a.w + b.w);
}

// prefetch a strided set of 128B lines of W_proj into L2 (hint; bounds-guarded)
#define WPROJ_LINES ((size_t)VT * HH * 4 / 128)    // 1,024,000
__device__ __forceinline__ void pf_chunk(const char* base, size_t line0,
                                         int nlines, int widx, int nworkers, int tid) {
    size_t l = line0 + (size_t)widx * 256 + tid;
    const size_t step = (size_t)nworkers * 256;
    #pragma unroll 2
    for (int i = 0; i < nlines; i++) {
        if (l < WPROJ_LINES)
            asm volatile("prefetch.global.L2 [%0];" :: "l"(base + (l << 7)));
        l += step;
    }
}

// grid barrier: all GRID CTAs co-resident (launch_bounds(256,2), 55KB smem)
__device__ __forceinline__ void gbar(unsigned target) {
    __syncthreads();
    __threadfence();
    if (threadIdx.x == 0) {
        atomicAdd(&g_bar_cnt, 1u);
        while (*(volatile unsigned*)&g_bar_cnt < target) __nanosleep(64);
    }
    __syncthreads();
}

__global__ void init_bar() { g_bar_cnt = 0; }

// ---------------- tf32 GEMM tile bodies ----------------
#define PLDA 36
#define PBUF (64 * PLDA + 128 * PLDA)
#define GTC_SMEM (2 * PBUF * 4)

// split-K tile -> transposed partials (p = split index)
__device__ void gemm_sk_tile(float* sm, int tid, int n0, int kbase, int kslice,
    const float* __restrict__ A0, const float* __restrict__ B0, int K0,
    const float* __restrict__ A1, const float* __restrict__ B1, int K1,
    int N, int p)
{
    const int wid  = tid >> 5;
    const int lane = tid & 31;
    const int wm   = wid & 1;
    const int wn   = wid >> 1;
    const int lrow = tid >> 3;
    const int lf4  = tid & 7;

    float d[2][4][4];
    #pragma unroll
    for (int i = 0; i < 2; i++)
        #pragma unroll
        for (int j = 0; j < 4; j++)
            #pragma unroll
            for (int k = 0; k < 4; k++) d[i][j][k] = 0.f;

    auto load_tile = [&](int buf, int gk) {
        const float* A; const float* Bv; int K, kl;
        if (gk < K0) { A = A0; Bv = B0; K = K0; kl = gk; }
        else         { A = A1; Bv = B1; K = K1; kl = gk - K0; }
        float* as = sm + buf * PBUF;
        float* bs = as + 64 * PLDA;
        #pragma unroll
        for (int i = 0; i < 2; i++) {
            int row = lrow + i * 32;
            cp_async16(smem_u32(&as[row * PLDA + lf4 * 4]),
                       &A[(size_t)row * K + kl + lf4 * 4]);
        }
        #pragma unroll
        for (int i = 0; i < 4; i++) {
            int row = lrow + i * 32;
            cp_async16(smem_u32(&bs[row * PLDA + lf4 * 4]),
                       &Bv[(size_t)(n0 + row) * K + kl + lf4 * 4]);
        }
        cp_commit();
    };

    const int NT = kslice / 32;
    load_tile(0, kbase);
    for (int t = 0; t < NT; t++) {
        if (t + 1 < NT) load_tile((t + 1) & 1, kbase + (t + 1) * 32);
        else cp_commit();
        cp_wait1();
        __syncthreads();
        const float* as = sm + (t & 1) * PBUF;
        const float* bs = as + 64 * PLDA;
        const int r = lane >> 2, c = lane & 3;
        #pragma unroll
        for (int k8 = 0; k8 < 4; k8++) {
            int kc = k8 * 8;
            uint32_t af[2][4], bf[4][2];
            #pragma unroll
            for (int mm = 0; mm < 2; mm++) {
                int mb = wm * 32 + mm * 16;
                af[mm][0] = f2tf32(as[(mb + r)     * PLDA + kc + c]);
                af[mm][1] = f2tf32(as[(mb + r + 8) * PLDA + kc + c]);
                af[mm][2] = f2tf32(as[(mb + r)     * PLDA + kc + c + 4]);
                af[mm][3] = f2tf32(as[(mb + r + 8) * PLDA + kc + c + 4]);
            }
            #pragma unroll
            for (int nn = 0; nn < 4; nn++) {
                int nb = wn * 32 + nn * 8;
                bf[nn][0] = f2tf32(bs[(nb + r) * PLDA + kc + c]);
                bf[nn][1] = f2tf32(bs[(nb + r) * PLDA + kc + c + 4]);
            }
            #pragma unroll
            for (int mm = 0; mm < 2; mm++)
                #pragma unroll
                for (int nn = 0; nn < 4; nn++)
                    mma_tf32(d[mm][nn], af[mm], bf[nn]);
        }
        __syncthreads();
    }

    const int nq = N >> 2;
    #pragma unroll
    for (int mm = 0; mm < 2; mm++) {
        int m = wm * 32 + mm * 16 + (lane >> 2);
        #pragma unroll
        for (int nn = 0; nn < 4; nn++) {
            int n = n0 + wn * 32 + nn * 8 + (lane & 3) * 2;
            int w = n & 3;
            float* f0 = (float*)&g_part[((size_t)m * nq + (n >> 2)) * NSPLIT + p];
            float* f1 = (float*)&g_part[((size_t)(m + 8) * nq + (n >> 2)) * NSPLIT + p];
            *(float2*)(f0 + w) = make_float2(d[mm][nn][0], d[mm][nn][1]);
            *(float2*)(f1 + w) = make_float2(d[mm][nn][2], d[mm][nn][3]);
        }
    }
}

// projection tile -> C (+bias)
__device__ void gemm_proj_tile(float* sm, int tid, int n0,
    const float* __restrict__ A, const float* __restrict__ Bm,
    const float* __restrict__ bias, float* __restrict__ C)
{
    const int wid  = tid >> 5;
    const int lane = tid & 31;
    const int wm   = wid & 1;
    const int wn   = wid >> 1;
    const int lrow = tid >> 3;
    const int lf4  = tid & 7;

    float d[2][4][4];
    #pragma unroll
    for (int i = 0; i < 2; i++)
        #pragma unroll
        for (int j = 0; j < 4; j++)
            #pragma unroll
            for (int k = 0; k < 4; k++) d[i][j][k] = 0.f;

    auto load_tile = [&](int buf, int kb) {
        float* as = sm + buf * PBUF;
        float* bs = as + 64 * PLDA;
        #pragma unroll
        for (int i = 0; i < 2; i++) {
            int row = lrow + i * 32;
            cp_async16(smem_u32(&as[row * PLDA + lf4 * 4]),
                       &A[(size_t)row * HH + kb + lf4 * 4]);
        }
        #pragma unroll
        for (int i = 0; i < 4; i++) {
            int row = lrow + i * 32;
            cp_async16(smem_u32(&bs[row * PLDA + lf4 * 4]),
                       &Bm[(size_t)(n0 + row) * HH + kb + lf4 * 4]);
        }
        cp_commit();
    };

    const int NT = HH / 32;
    load_tile(0, 0);
    for (int t = 0; t < NT; t++) {
        if (t + 1 < NT) load_tile((t + 1) & 1, (t + 1) * 32);
        else cp_commit();
        cp_wait1();
        __syncthreads();
        const float* as = sm + (t & 1) * PBUF;
        const float* bs = as + 64 * PLDA;
        const int r = lane >> 2, c = lane & 3;
        #pragma unroll
        for (int k8 = 0; k8 < 4; k8++) {
            int kc = k8 * 8;
            uint32_t af[2][4], bf[4][2];
            #pragma unroll
            for (int mm = 0; mm < 2; mm++) {
                int mb = wm * 32 + mm * 16;
                af[mm][0] = f2tf32(as[(mb + r)     * PLDA + kc + c]);
                af[mm][1] = f2tf32(as[(mb + r + 8) * PLDA + kc + c]);
                af[mm][2] = f2tf32(as[(mb + r)     * PLDA + kc + c + 4]);
                af[mm][3] = f2tf32(as[(mb + r + 8) * PLDA + kc + c + 4]);
            }
            #pragma unroll
            for (int nn = 0; nn < 4; nn++) {
                int nb = wn * 32 + nn * 8;
                bf[nn][0] = f2tf32(bs[(nb + r) * PLDA + kc + c]);
                bf[nn][1] = f2tf32(bs[(nb + r) * PLDA + kc + c + 4]);
            }
            #pragma unroll
            for (int mm = 0; mm < 2; mm++)
                #pragma unroll
                for (int nn = 0; nn < 4; nn++)
                    mma_tf32(d[mm][nn], af[mm], bf[nn]);
        }
        __syncthreads();
    }

    #pragma unroll
    for (int mm = 0; mm < 2; mm++) {
        int m = wm * 32 + mm * 16 + (lane >> 2);
        #pragma unroll
        for (int nn = 0; nn < 4; nn++) {
            int n = n0 + wn * 32 + nn * 8 + (lane & 3) * 2;
            float2 bv = *(const float2*)&bias[n];
            *(float2*)&C[(size_t)m * VT + n] =
                make_float2(d[mm][nn][0] + bv.x, d[mm][nn][1] + bv.y);
            *(float2*)&C[(size_t)(m + 8) * VT + n] =
                make_float2(d[mm][nn][2] + bv.x, d[mm][nn][3] + bv.y);
        }
    }
}

// reduce partials + bias(es) (+tanh); __ldcg: g_part re-read across phases
__device__ void reduce_phase(int cta, int tid,
    const float* __restrict__ bias0, const float* __restrict__ bias1,
    float* __restrict__ C, int N, int do_tanh)
{
    const int lane = tid & 31;
    const int gw   = cta * 8 + (tid >> 5);
    const int o    = gw * 8 + (lane >> 2);
    const int q    = lane & 3;
    const int nq   = N >> 2;
    const int m    = o / nq;
    const int n4   = o - m * nq;

    const float4* srcp = &g_part[(size_t)o * NSPLIT + q * 4];
    float4 s = __ldcg(srcp);
    s = f4add(s, __ldcg(srcp + 1));
    s = f4add(s, __ldcg(srcp + 2));
    s = f4add(s, __ldcg(srcp + 3));
    #pragma unroll
    for (int off = 2; off >= 1; off >>= 1) {
        s.x += __shfl_down_sync(0xffffffffu, s.x, off, 4);
        s.y += __shfl_down_sync(0xffffffffu, s.y, off, 4);
        s.z += __shfl_down_sync(0xffffffffu, s.z, off, 4);
        s.w += __shfl_down_sync(0xffffffffu, s.w, off, 4);
    }
    if (q == 0) {
        s = f4add(s, *(const float4*)&bias0[n4 * 4]);
        if (bias1) s = f4add(s, *(const float4*)&bias1[n4 * 4]);
        if (do_tanh) {
            s.x = tanhf(s.x); s.y = tanhf(s.y); s.z = tanhf(s.z); s.w = tanhf(s.w);
        }
        *(float4*)&C[(size_t)m * N + n4 * 4] = s;
    }
}

// ---------------- the mega kernel ----------------
__global__ __launch_bounds__(256, 2) void mega_kernel(
    const int* __restrict__ src, const int* __restrict__ pos, const int* __restrict__ tgt,
    const float* __restrict__ emb_in, const float* __restrict__ emb_out,
    const float* __restrict__ emb_pos,
    const float* __restrict__ W_scale, const float* __restrict__ b_scale,
    const float* __restrict__ W_ih, const float* __restrict__ b_ih,
    const float* __restrict__ W_hh, const float* __restrict__ b_hh,
    const float* __restrict__ W_proj, const float* __restrict__ b_proj,
    float* __restrict__ out, float* __restrict__ h)
{
    extern __shared__ float sm[];
    __shared__ float s_h0[HH];
    __shared__ float s_w[128];
    __shared__ int s_sidx[32], s_pidx[32];

    const int cta = blockIdx.x;
    const int tid = threadIdx.x;
    const int lane = tid & 31;
    const int warp = tid >> 5;
    unsigned gen = 0;
    const char* wp = (const char*)W_proj;

    // ---- P0: mean partials (all 256: b = cta>>2, y = cta&3) ----
    {
        int b = cta >> 2, y = cta & 3;
        int s0 = y * (SS / SCH);
        if (tid >= 32 && tid < 32 + SS / SCH) s_sidx[tid - 32] = src[b * SS + s0 + tid - 32];
        if (tid >= 64 && tid < 64 + SS / SCH) s_pidx[tid - 64] = pos[b * SS + s0 + tid - 64];
        __syncthreads();
        const int half = tid >= 128;
        const int cc = half ? tid * 4 - EE : tid * 4;
        const float* base = half ? emb_pos : emb_in;
        const int* idx = half ? s_pidx : s_sidx;
        float4 acc = make_float4(0.f, 0.f, 0.f, 0.f);
        #pragma unroll 5
        for (int i = 0; i < SS / SCH; i++)
            acc = f4add(acc, *(const float4*)(base + (size_t)idx[i] * EE + cc));
        *(float4*)(g_mpart + ((size_t)y * BB + b) * HH + tid * 4) = acc;
    }
    gbar(++gen * GRID);

    // ---- P1: mean reduce (ctas 0..63); others prefetch W_proj [0 .. 196608) ----
    if (cta < BB) {
        int c4 = tid * 4;
        float4 s = make_float4(0.f, 0.f, 0.f, 0.f);
        #pragma unroll
        for (int y = 0; y < SCH; y++)
            s = f4add(s, __ldcg((const float4*)(g_mpart + ((size_t)y * BB + cta) * HH + c4)));
        const float inv = 1.0f / SS;
        s.x *= inv; s.y *= inv; s.z *= inv; s.w *= inv;
        *(float4*)(g_mean + cta * HH + c4) = s;
    } else {
        pf_chunk(wp, 0, 4, cta - 64, 192, tid);
    }
    gbar(++gen * GRID);

    // ---- P2: h0 GEMM (ctas 0..127); others prefetch [196608 .. 458752) ----
    if (cta < 8 * NSPLIT) {
        int bx = cta & 7, p = cta >> 3;
        const int ks = HH / NSPLIT;
        gemm_sk_tile(sm, tid, bx * 128, p * ks, ks,
                     g_mean, W_scale, HH, nullptr, nullptr, 0, HH, p);
    } else {
        pf_chunk(wp, 196608, 8, cta - 128, 128, tid);
    }
    gbar(++gen * GRID);

    // ---- P3: reduce -> g_h0 ----
    reduce_phase(cta, tid, b_scale, nullptr, g_h0, HH, 0);
    gbar(++gen * GRID);

    // ---- P4: energies (all 256) + 2-line prefetch [458752 .. 589824) ----
    {
        int b = cta >> 2, y = cta & 3;
        int s0 = y * (SS / SCH);
        for (int c = tid; c < HH; c += 256) s_h0[c] = g_h0[b * HH + c];
        if (tid >= 32 && tid < 32 + SS / SCH) s_sidx[tid - 32] = src[b * SS + s0 + tid - 32];
        if (tid >= 64 && tid < 64 + SS / SCH) s_pidx[tid - 64] = pos[b * SS + s0 + tid - 64];
        pf_chunk(wp, 458752, 2, cta, 256, tid);
        __syncthreads();
        for (int i = warp; i < SS / SCH; i += 8) {
            const float4* rw = (const float4*)(emb_in  + (size_t)s_sidx[i] * EE);
            const float4* rp = (const float4*)(emb_pos + (size_t)s_pidx[i] * EE);
            float sum = 0.f;
            #pragma unroll
            for (int e = 0; e < 8; e++) {
                int f4 = lane + e * 32;
                float4 v = (f4 < 128) ? rw[f4] : rp[f4 - 128];
                int c = f4 * 4;
                sum = fmaf(s_h0[c],   v.x, sum);
                sum = fmaf(s_h0[c+1], v.y, sum);
                sum = fmaf(s_h0[c+2], v.z, sum);
                sum = fmaf(s_h0[c+3], v.w, sum);
            }
            #pragma unroll
            for (int o = 16; o; o >>= 1) sum += __shfl_xor_sync(0xffffffffu, sum, o);
            if (lane == 0) g_en[b * SS + s0 + i] = sum;
        }
    }
    gbar(++gen * GRID);

    // ---- P5: softmax + context partials (all 256) + 2-line prefetch [589824 .. 720896) ----
    {
        int b = cta >> 2, y = cta & 3;
        int s0 = y * (SS / SCH);
        if (tid < 32) {
            float e[4];
            float m = -1e30f;
            #pragma unroll
            for (int i = 0; i < 4; i++) {
                int s = lane + i * 32;
                e[i] = (s < SS) ? __ldcg(&g_en[b * SS + s]) : -1e30f;
                m = fmaxf(m, e[i]);
            }
            #pragma unroll
            for (int o = 16; o; o >>= 1) m = fmaxf(m, __shfl_xor_sync(0xffffffffu, m, o));
            float sum = 0.f;
            #pragma unroll
            for (int i = 0; i < 4; i++) { e[i] = __expf(e[i] - m); sum += e[i]; }
            #pragma unroll
            for (int o = 16; o; o >>= 1) sum += __shfl_xor_sync(0xffffffffu, sum, o);
            float inv = 1.0f / (sum * (float)SS);
            #pragma unroll
            for (int i = 0; i < 4; i++) {
                int s = lane + i * 32;
                if (s < 128) s_w[s] = e[i] * inv;
            }
        }
        if (tid >= 32 && tid < 32 + SS / SCH) s_sidx[tid - 32] = src[b * SS + s0 + tid - 32];
        if (tid >= 64 && tid < 64 + SS / SCH) s_pidx[tid - 64] = pos[b * SS + s0 + tid - 64];
        pf_chunk(wp, 589824, 2, cta, 256, tid);
        __syncthreads();
        const int half = tid >= 128;
        const int cc = half ? tid * 4 - EE : tid * 4;
        const float* base = half ? emb_pos : emb_in;
        const int* idx = half ? s_pidx : s_sidx;
        float4 acc = make_float4(0.f, 0.f, 0.f, 0.f);
        #pragma unroll 5
        for (int i = 0; i < SS / SCH; i++) {
            float ws = s_w[s0 + i];
            float4 v = *(const float4*)(base + (size_t)idx[i] * EE + cc);
            acc.x = fmaf(ws, v.x, acc.x); acc.y = fmaf(ws, v.y, acc.y);
            acc.z = fmaf(ws, v.z, acc.z); acc.w = fmaf(ws, v.w, acc.w);
        }
        *(float4*)(g_cpart + ((size_t)y * BB + b) * HH + tid * 4) = acc;
    }
    gbar(++gen * GRID);

    // ---- P6: build x (ctas 0..63); others prefetch [720896 .. 917504) ----
    if (cta < BB) {
        float4* dst = (float4*)(g_x + cta * (EE + HH));
        if (tid < 128) {
            const float4* w = (const float4*)(emb_out + (size_t)tgt[cta] * EE);
            dst[tid] = w[tid];
        }
        float4 s = make_float4(0.f, 0.f, 0.f, 0.f);
        #pragma unroll
        for (int y = 0; y < SCH; y++)
            s = f4add(s, __ldcg((const float4*)(g_cpart + ((size_t)y * BB + cta) * HH + tid * 4)));
        dst[128 + tid] = s;
    } else {
        pf_chunk(wp, 720896, 4, cta - 64, 192, tid);
    }
    gbar(++gen * GRID);

    // ---- P7: decoder GEMM (ctas 0..127); others prefetch [917504 .. end) ----
    if (cta < 8 * NSPLIT) {
        int bx = cta & 7, p = cta >> 3;
        const int ks = (EE + HH + HH) / NSPLIT;   // 160
        gemm_sk_tile(sm, tid, bx * 128, p * ks, ks,
                     g_x, W_ih, EE + HH, g_h0, W_hh, HH, HH, p);
    } else {
        pf_chunk(wp, 917504, 4, cta - 128, 128, tid);
    }
    gbar(++gen * GRID);

    // ---- P8: reduce -> h (with tanh) ----
    reduce_phase(cta, tid, b_ih, b_hh, h, HH, 1);
    gbar(++gen * GRID);

    // ---- P9: projection (ctas 0..249) ----
    if (cta < VT / 128) {
        gemm_proj_tile(sm, tid, cta * 128, h, W_proj, b_proj, out);
    }
}

// ---------------- launch ----------------
extern "C" void kernel_launch(void* const* d_in, const int* in_sizes, int n_in,
                              void* d_out, int out_size)
{
    const int* src = (const int*)d_in[0];
    const int* pos = (const int*)d_in[1];
    const int* tgt = (const int*)d_in[2];

    int iE = -1;
    for (int i = 3; i < n_in; i++) {
        if (in_sizes[i] == 32000 * 512) { iE = i; break; }
    }
    const float* emb_in  = (const float*)d_in[iE + 0];
    const float* emb_out = (const float*)d_in[iE + 1];
    const float* emb_pos = (const float*)d_in[iE + 2];
    const float* W_scale = (const float*)d_in[iE + 3];
    const float* b_scale = (const float*)d_in[iE + 4];
    const float* W_ih    = (const float*)d_in[iE + 5];
    const float* b_ih    = (const float*)d_in[iE + 6];
    const float* W_hh    = (const float*)d_in[iE + 7];
    const float* b_hh    = (const float*)d_in[iE + 8];
    const float* W_proj  = (const float*)d_in[iE + 9];
    const float* b_proj  = (const float*)d_in[iE + 10];

    float* out = (float*)d_out;            // [B,VT]
    float* h   = out + (size_t)BB * VT;    // [B,H]

    cudaFuncSetAttribute(mega_kernel,
                         cudaFuncAttributeMaxDynamicSharedMemorySize, GTC_SMEM);

    init_bar<<<1, 1>>>();
    mega_kernel<<<GRID, 256, GTC_SMEM>>>(
        src, pos, tgt, emb_in, emb_out, emb_pos,
        W_scale, b_scale, W_ih, b_ih, W_hh, b_hh, W_proj, b_proj,
        out, h);

    (void)out_size;
}